// round 3
// baseline (speedup 1.0000x reference)
#include <cuda_runtime.h>

// CELossWithLS: focal-weighted label-smoothed CE, single pass over logits.
// logits: [B*S, C] f32 (C = 10000), target: [B*S] int32 (JAX x64 disabled ->
// jnp.int64 silently coerces to int32; round-2 crash was reading it as i64),
// out: scalar f32.
//
// per_tok = -( 1e-5 * sum_i (1-p_i)^3 * logs_i  +  0.9 * (1-p_t)^3 * logs_t )
// Expansion: sum_i (1-p)^3 logs = (Sx - C*L) - 3*(B1/A1 - L) + O(1.5e-5 abs)
// with A1 = sum e^x, B1 = sum x e^x, L = log(A1).
// Dropped p^2/p^3 terms carry the 1e-5 smoothing weight and are bounded by
// max_p p^2|ln p| = 0.18 summed -> ~1.5e-5 abs vs per-token loss ~8.8
// -> ~2e-6 relative, far under the 1e-3 gate.

#define NCLASS  10000
#define NVEC    (NCLASS / 4)   // 2500 float4 per row
#define THREADS 256

__device__ double g_sum;
__device__ double g_cnt;

__global__ void ce_init() {
    g_sum = 0.0;
    g_cnt = 0.0;
}

__global__ __launch_bounds__(THREADS, 1) void ce_main(
    const float* __restrict__ logits,
    const int*   __restrict__ target)
{
    const int row = blockIdx.x;
    const int tgt = __ldg(&target[row]);

    const float4* __restrict__ p =
        reinterpret_cast<const float4*>(logits) + (size_t)row * NVEC;

    float sx = 0.0f;   // sum x
    float a1 = 0.0f;   // sum e^x
    float b1 = 0.0f;   // sum x * e^x

    #pragma unroll 2
    for (int i = threadIdx.x; i < NVEC; i += THREADS) {
        float4 v = p[i];
        float e;
        e = __expf(v.x); sx += v.x; a1 += e; b1 = fmaf(v.x, e, b1);
        e = __expf(v.y); sx += v.y; a1 += e; b1 = fmaf(v.y, e, b1);
        e = __expf(v.z); sx += v.z; a1 += e; b1 = fmaf(v.z, e, b1);
        e = __expf(v.w); sx += v.w; a1 += e; b1 = fmaf(v.w, e, b1);
    }

    // intra-warp tree reduce (3 values)
    #pragma unroll
    for (int o = 16; o > 0; o >>= 1) {
        sx += __shfl_down_sync(0xffffffffu, sx, o);
        a1 += __shfl_down_sync(0xffffffffu, a1, o);
        b1 += __shfl_down_sync(0xffffffffu, b1, o);
    }

    __shared__ float s_sx[THREADS / 32];
    __shared__ float s_a1[THREADS / 32];
    __shared__ float s_b1[THREADS / 32];
    const int lane = threadIdx.x & 31;
    const int wrp  = threadIdx.x >> 5;
    if (lane == 0) { s_sx[wrp] = sx; s_a1[wrp] = a1; s_b1[wrp] = b1; }
    __syncthreads();

    if (threadIdx.x == 0) {
        float SX = 0.0f, A1 = 0.0f, B1 = 0.0f;
        #pragma unroll
        for (int k = 0; k < THREADS / 32; k++) {
            SX += s_sx[k]; A1 += s_a1[k]; B1 += s_b1[k];
        }
        if (tgt >= 0 && tgt < NCLASS) {   // bound-checked gather: never fault
            // accurate log: its error is multiplied by C=1e4 in (SX - C*L),
            // so use logf, not __logf. Once per row -> cost irrelevant.
            float L  = logf(A1);
            float S3 = (SX - (float)NCLASS * L) - 3.0f * (B1 / A1 - L);

            float xt = __ldg(&logits[(size_t)row * NCLASS + tgt]);
            float lt = xt - L;                  // log-prob of target
            float pt = __expf(lt);
            float om = 1.0f - pt;
            float per_tok = -(1e-5f * S3 + 0.9f * om * om * om * lt);

            atomicAdd(&g_sum, (double)per_tok);
            atomicAdd(&g_cnt, 1.0);
        }
    }
}

__global__ void ce_fin(float* __restrict__ out) {
    out[0] = (float)(g_sum / g_cnt);
}

extern "C" void kernel_launch(void* const* d_in, const int* in_sizes, int n_in,
                              void* d_out, int out_size)
{
    const float* logits = (const float*)d_in[0];
    const int*   target = (const int*)d_in[1];
    const int ntok = in_sizes[1];          // B*S tokens (element count)

    ce_init<<<1, 1>>>();
    ce_main<<<ntok, THREADS>>>(logits, target);
    ce_fin<<<1, 1>>>((float*)d_out);
}